// round 1
// baseline (speedup 1.0000x reference)
#include <cuda_runtime.h>

// Fused: out = f(X @ W^T) with
//   o   = relu(1 - beta + rowsum)
//   res = relu(1 - (beta_res - (x + o)))
//   out = res >= 0 ? res : 0.02*res   (identity after relu, kept literally)
//
// Shapes fixed: B = N = K = 4096, fp32.

#define BM 128
#define BN 128
#define BK 16
#define TM 8
#define TN 8
#define NTHREADS 256

__global__ void __launch_bounds__(NTHREADS, 2)
resfc_fused_gemm(const float* __restrict__ X,
                 const float* __restrict__ W,
                 const float* __restrict__ beta,
                 const float* __restrict__ beta_res,
                 float* __restrict__ out,
                 int N, int K)
{
    __shared__ float As[BK][BM];   // X tile, transposed: As[k][m]
    __shared__ float Bs[BK][BN];   // W tile, transposed: Bs[k][n]

    const int tid = threadIdx.x;
    const int tx  = tid & 15;      // 0..15 -> n direction
    const int ty  = tid >> 4;      // 0..15 -> m direction

    const int rowBase = blockIdx.y * BM;   // batch rows
    const int colBase = blockIdx.x * BN;   // output cols (W rows)

    // Global->shared load mapping: 256 threads, each thread loads
    // 2x float4 from X and 2x float4 from W per BK step.
    // lrow in [0,64), second pass covers rows +64. lk = 4*(tid&3).
    const int lrow = tid >> 2;          // 0..63
    const int lk   = (tid & 3) << 2;    // 0,4,8,12

    const float* Xb = X + (size_t)(rowBase + lrow) * K + lk;
    const float* Wb = W + (size_t)(colBase + lrow) * K + lk;

    float acc[TM][TN];
    #pragma unroll
    for (int i = 0; i < TM; ++i)
        #pragma unroll
        for (int j = 0; j < TN; ++j)
            acc[i][j] = 0.0f;

    for (int k0 = 0; k0 < K; k0 += BK) {
        // ---- load tiles (transpose into shared) ----
        #pragma unroll
        for (int p = 0; p < 2; ++p) {
            const int r = lrow + p * 64;
            float4 xv = *reinterpret_cast<const float4*>(Xb + (size_t)p * 64 * K + k0);
            As[lk + 0][r] = xv.x;
            As[lk + 1][r] = xv.y;
            As[lk + 2][r] = xv.z;
            As[lk + 3][r] = xv.w;
            float4 wv = *reinterpret_cast<const float4*>(Wb + (size_t)p * 64 * K + k0);
            Bs[lk + 0][r] = wv.x;
            Bs[lk + 1][r] = wv.y;
            Bs[lk + 2][r] = wv.z;
            Bs[lk + 3][r] = wv.w;
        }
        __syncthreads();

        // ---- compute ----
        #pragma unroll
        for (int kk = 0; kk < BK; ++kk) {
            float a[TM], b[TN];
            float4 a0 = *reinterpret_cast<const float4*>(&As[kk][ty * TM]);
            float4 a1 = *reinterpret_cast<const float4*>(&As[kk][ty * TM + 4]);
            float4 b0 = *reinterpret_cast<const float4*>(&Bs[kk][tx * TN]);
            float4 b1 = *reinterpret_cast<const float4*>(&Bs[kk][tx * TN + 4]);
            a[0]=a0.x; a[1]=a0.y; a[2]=a0.z; a[3]=a0.w;
            a[4]=a1.x; a[5]=a1.y; a[6]=a1.z; a[7]=a1.w;
            b[0]=b0.x; b[1]=b0.y; b[2]=b0.z; b[3]=b0.w;
            b[4]=b1.x; b[5]=b1.y; b[6]=b1.z; b[7]=b1.w;
            #pragma unroll
            for (int i = 0; i < TM; ++i)
                #pragma unroll
                for (int j = 0; j < TN; ++j)
                    acc[i][j] = fmaf(a[i], b[j], acc[i][j]);
        }
        __syncthreads();
    }

    // ---- fused epilogue ----
    const float beta0   = beta[0];
    const float one_mb  = 1.0f - beta0;
    const int   cBase   = colBase + tx * TN;

    float br[TN];
    {
        float4 br0 = *reinterpret_cast<const float4*>(beta_res + cBase);
        float4 br1 = *reinterpret_cast<const float4*>(beta_res + cBase + 4);
        br[0]=br0.x; br[1]=br0.y; br[2]=br0.z; br[3]=br0.w;
        br[4]=br1.x; br[5]=br1.y; br[6]=br1.z; br[7]=br1.w;
    }

    #pragma unroll
    for (int i = 0; i < TM; ++i) {
        const int r = rowBase + ty * TM + i;
        const float* xrow = X + (size_t)r * N + cBase;
        float4 x0 = *reinterpret_cast<const float4*>(xrow);
        float4 x1 = *reinterpret_cast<const float4*>(xrow + 4);
        float xv[TN] = {x0.x, x0.y, x0.z, x0.w, x1.x, x1.y, x1.z, x1.w};

        float res[TN];
        #pragma unroll
        for (int j = 0; j < TN; ++j) {
            float o = fmaxf(one_mb + acc[i][j], 0.0f);
            float v = 1.0f - (br[j] - (xv[j] + o));
            float rr = fmaxf(v, 0.0f);
            res[j] = (rr >= 0.0f) ? rr : 0.02f * rr;
        }
        float* orow = out + (size_t)r * N + cBase;
        *reinterpret_cast<float4*>(orow)     = make_float4(res[0], res[1], res[2], res[3]);
        *reinterpret_cast<float4*>(orow + 4) = make_float4(res[4], res[5], res[6], res[7]);
    }
}

extern "C" void kernel_launch(void* const* d_in, const int* in_sizes, int n_in,
                              void* d_out, int out_size)
{
    const float* x        = (const float*)d_in[0];
    const float* W        = (const float*)d_in[1];
    const float* beta     = (const float*)d_in[2];
    const float* beta_res = (const float*)d_in[3];
    float* out            = (float*)d_out;

    const int N = 4096;
    const int K = 4096;

    dim3 grid(N / BN, 4096 / BM);   // 32 x 32 = 1024 CTAs
    dim3 block(NTHREADS);
    resfc_fused_gemm<<<grid, block>>>(x, W, beta, beta_res, out, N, K);
}

// round 3
// speedup vs baseline: 4.8387x; 4.8387x over previous
// mma.sync tf32 fused GEMM+epilogue for ResFCEventuallyLayer (B=N=K=4096, fp32).
// Harness PTX targets compute_103 (no 'a') -> tcgen05/TMEM unavailable; use the
// baseline-PTX tensor path: ldmatrix + mma.sync.m16n8k8.tf32 with cp.async pipeline.
//   out = relu(1 - beta + X@W^T); res = relu(1 - beta_res + x + out); leaky==id.
// Accuracy: X,W pre-rounded to tf32 with cvt.rna (unbiased) in __device__ scratch.

#include <cuda_runtime.h>
#include <cstdint>

#define DIM     4096
#define BM      128
#define BN      128
#define BK      32
#define STAGES  3
#define NT      256
#define NC      (DIM / BK)            // 128 k-chunks
#define AB_TILE (BM * BK * 4)          // 16384 bytes per matrix per stage
#define STAGE_BYTES (2 * AB_TILE)      // 32768
#define SMEM_TOTAL  (STAGES * STAGE_BYTES)  // 98304

// ------------------------------------------------------------------ scratch
__device__ float g_Xr[(size_t)DIM * DIM];
__device__ float g_Wr[(size_t)DIM * DIM];

// ------------------------------------------------------------------ helpers
__device__ __forceinline__ uint32_t smem_u32(const void* p) {
    uint32_t a;
    asm("{ .reg .u64 t; cvta.to.shared.u64 t, %1; cvt.u32.u64 %0, t; }" : "=r"(a) : "l"(p));
    return a;
}
__device__ __forceinline__ void cp16(uint32_t saddr, const void* gaddr) {
    asm volatile("cp.async.cg.shared.global [%0], [%1], 16;"
                 :: "r"(saddr), "l"(gaddr) : "memory");
}
__device__ __forceinline__ void cp_commit() {
    asm volatile("cp.async.commit_group;" ::: "memory");
}
template <int N>
__device__ __forceinline__ void cp_wait() {
    asm volatile("cp.async.wait_group %0;" :: "n"(N) : "memory");
}
__device__ __forceinline__ void ldsm4(uint32_t* r, uint32_t addr) {
    asm volatile("ldmatrix.sync.aligned.m8n8.x4.shared.b16 {%0,%1,%2,%3}, [%4];"
                 : "=r"(r[0]), "=r"(r[1]), "=r"(r[2]), "=r"(r[3]) : "r"(addr));
}
__device__ __forceinline__ void mma_tf32(float* d, const uint32_t* a, const uint32_t* b) {
    asm volatile(
        "mma.sync.aligned.m16n8k8.row.col.f32.tf32.tf32.f32 "
        "{%0,%1,%2,%3}, {%4,%5,%6,%7}, {%8,%9}, {%0,%1,%2,%3};"
        : "+f"(d[0]), "+f"(d[1]), "+f"(d[2]), "+f"(d[3])
        : "r"(a[0]), "r"(a[1]), "r"(a[2]), "r"(a[3]), "r"(b[0]), "r"(b[1]));
}

// ------------------------------------------------------------------ prep kernel
__global__ void __launch_bounds__(256) round_tf32_kernel(const float* __restrict__ in,
                                                         float* __restrict__ outp) {
    size_t i = ((size_t)blockIdx.x * blockDim.x + threadIdx.x) * 4;
    float4 v = *reinterpret_cast<const float4*>(in + i);
    uint32_t a, b, c, d;
    asm("cvt.rna.tf32.f32 %0, %1;" : "=r"(a) : "f"(v.x));
    asm("cvt.rna.tf32.f32 %0, %1;" : "=r"(b) : "f"(v.y));
    asm("cvt.rna.tf32.f32 %0, %1;" : "=r"(c) : "f"(v.z));
    asm("cvt.rna.tf32.f32 %0, %1;" : "=r"(d) : "f"(v.w));
    *reinterpret_cast<float4*>(outp + i) =
        make_float4(__uint_as_float(a), __uint_as_float(b),
                    __uint_as_float(c), __uint_as_float(d));
}

// ------------------------------------------------------------------ main kernel
__global__ void __launch_bounds__(NT, 2)
resfc_mma_gemm(const float* __restrict__ Ar,   // tf32-rounded X
               const float* __restrict__ Br,   // tf32-rounded W
               const float* __restrict__ X,    // original X (residual)
               const float* __restrict__ beta,
               const float* __restrict__ beta_res,
               float* __restrict__ out)
{
    extern __shared__ __align__(1024) char smem[];
    const uint32_t sbase = smem_u32(smem);
    const int tid = threadIdx.x;
    const int l   = tid & 31;
    const int wid = tid >> 5;
    const int warpM = (wid & 1) * 64;     // 2 warps in M
    const int warpN = (wid >> 1) * 32;    // 4 warps in N
    const int bm = blockIdx.y * BM;
    const int bn = blockIdx.x * BN;

    // ---- cp.async mapping: 256 threads x 4 passes x (A16B + B16B) per stage
    const int grow = tid >> 3;            // row 0..31 (+32 per pass)
    const int gcol = tid & 7;             // 16B granule within 128B row
    const float* gA = Ar + (size_t)(bm + grow) * DIM + gcol * 4;
    const float* gB = Br + (size_t)(bn + grow) * DIM + gcol * 4;
    const uint32_t scol = (uint32_t)(gcol * 16);

    // ---- ldmatrix per-thread terms (SW128 swizzle within tile)
    const uint32_t xorv   = (uint32_t)(l & 7) << 4;
    const uint32_t aRow   = (uint32_t)(warpM + (l & 15));
    const uint32_t aByteH = (uint32_t)(l & 16);            // 0 or 16
    const uint32_t bRow   = (uint32_t)(warpN + (l & 7) + ((l >> 1) & 8));
    const uint32_t bByteH = (uint32_t)((l & 8) << 1);      // 0 or 16

    float acc[4][4][4];
    #pragma unroll
    for (int i = 0; i < 4; ++i)
        #pragma unroll
        for (int j = 0; j < 4; ++j)
            #pragma unroll
            for (int k = 0; k < 4; ++k)
                acc[i][j][k] = 0.0f;

    // -------- stage loader --------
    #define ISSUE(c, stage) do {                                              \
        const uint32_t sa_ = sbase + (uint32_t)(stage) * STAGE_BYTES;         \
        const float* ga_ = gA + (size_t)(c) * BK;                             \
        const float* gb_ = gB + (size_t)(c) * BK;                             \
        _Pragma("unroll")                                                     \
        for (int p_ = 0; p_ < 4; ++p_) {                                      \
            const uint32_t r_  = (uint32_t)(grow + p_ * 32);                  \
            const uint32_t so_ = r_ * 128 + (scol ^ ((r_ & 7) << 4));         \
            cp16(sa_ + so_,            ga_ + (size_t)p_ * 32 * DIM);          \
            cp16(sa_ + AB_TILE + so_,  gb_ + (size_t)p_ * 32 * DIM);          \
        }                                                                     \
    } while (0)

    // -------- prologue: fill STAGES-1 stages --------
    ISSUE(0, 0); cp_commit();
    ISSUE(1, 1); cp_commit();

    int stage = 0;
    for (int c = 0; c < NC; ++c) {
        cp_wait<STAGES - 2>();
        __syncthreads();

        const uint32_t aBase = sbase + (uint32_t)stage * STAGE_BYTES + aRow * 128;
        const uint32_t bBase = sbase + (uint32_t)stage * STAGE_BYTES + AB_TILE + bRow * 128;

        #pragma unroll
        for (int s = 0; s < 4; ++s) {       // 4 x k8 per 32-float chunk
            uint32_t aF[4][4];
            uint32_t bF[4][2];
            const uint32_t aoff = ((uint32_t)(s * 32) + aByteH) ^ xorv;
            const uint32_t boff = ((uint32_t)(s * 32) + bByteH) ^ xorv;
            #pragma unroll
            for (int t = 0; t < 4; ++t)
                ldsm4(aF[t], aBase + (uint32_t)t * 2048 + aoff);
            #pragma unroll
            for (int u = 0; u < 2; ++u) {
                uint32_t r[4];
                ldsm4(r, bBase + (uint32_t)u * 2048 + boff);
                bF[2 * u][0]     = r[0];  bF[2 * u][1]     = r[1];
                bF[2 * u + 1][0] = r[2];  bF[2 * u + 1][1] = r[3];
            }
            #pragma unroll
            for (int mt = 0; mt < 4; ++mt)
                #pragma unroll
                for (int nt = 0; nt < 4; ++nt)
                    mma_tf32(acc[mt][nt], aF[mt], bF[nt]);
        }

        __syncthreads();
        const int cn = c + STAGES - 1;
        if (cn < NC) {
            const int sn = (stage + STAGES - 1) % STAGES;
            ISSUE(cn, sn);
        }
        cp_commit();
        if (++stage == STAGES) stage = 0;
    }
    #undef ISSUE

    // -------- fused epilogue --------
    const float one_mb = 1.0f - beta[0];
    const int colB = bn + warpN + 2 * (l & 3);

    float2 br2[4];
    #pragma unroll
    for (int nt = 0; nt < 4; ++nt)
        br2[nt] = *reinterpret_cast<const float2*>(beta_res + colB + nt * 8);

    #pragma unroll
    for (int mt = 0; mt < 4; ++mt) {
        #pragma unroll
        for (int h = 0; h < 2; ++h) {
            const int row = bm + warpM + mt * 16 + (l >> 2) + h * 8;
            const float* xr  = X   + (size_t)row * DIM + colB;
            float*       orw = out + (size_t)row * DIM + colB;
            #pragma unroll
            for (int nt = 0; nt < 4; ++nt) {
                float2 xv = *reinterpret_cast<const float2*>(xr + nt * 8);
                const float d0 = acc[mt][nt][h * 2 + 0];
                const float d1 = acc[mt][nt][h * 2 + 1];
                const float o0 = fmaxf(one_mb + d0, 0.0f);
                const float o1 = fmaxf(one_mb + d1, 0.0f);
                const float r0 = fmaxf(1.0f - (br2[nt].x - (xv.x + o0)), 0.0f);
                const float r1 = fmaxf(1.0f - (br2[nt].y - (xv.y + o1)), 0.0f);
                *reinterpret_cast<float2*>(orw + nt * 8) = make_float2(r0, r1);
            }
        }
    }
}

// ------------------------------------------------------------------ host side
extern "C" void kernel_launch(void* const* d_in, const int* in_sizes, int n_in,
                              void* d_out, int out_size)
{
    const float* X        = (const float*)d_in[0];
    const float* W        = (const float*)d_in[1];
    const float* beta     = (const float*)d_in[2];
    const float* beta_res = (const float*)d_in[3];
    float* out            = (float*)d_out;

    void *pXr = nullptr, *pWr = nullptr;
    cudaGetSymbolAddress(&pXr, g_Xr);
    cudaGetSymbolAddress(&pWr, g_Wr);

    round_tf32_kernel<<<DIM * DIM / (256 * 4), 256>>>(X, (float*)pXr);
    round_tf32_kernel<<<DIM * DIM / (256 * 4), 256>>>(W, (float*)pWr);

    cudaFuncSetAttribute(resfc_mma_gemm,
                         cudaFuncAttributeMaxDynamicSharedMemorySize, SMEM_TOTAL);
    dim3 grid(DIM / BN, DIM / BM);   // 32 x 32
    resfc_mma_gemm<<<grid, NT, SMEM_TOTAL>>>((const float*)pXr, (const float*)pWr,
                                             X, beta, beta_res, out);
}

// round 4
// speedup vs baseline: 9.0167x; 1.8635x over previous
// mma.sync fp16 fused GEMM+epilogue for ResFCEventuallyLayer (B=N=K=4096, fp32).
// fp16 significand (11 bits) == tf32 significand, so accuracy matches the passing
// tf32 version (~2.9e-4) while m16n8k16.f16 doubles FLOP/instr and halves smem/L2
// traffic. X,W pre-converted (RN) to __half in __device__ scratch.
//   out = relu(1 - beta + X@W^T); res = relu(1 - beta_res + x + out); leaky==id.

#include <cuda_runtime.h>
#include <cuda_fp16.h>
#include <cstdint>

#define DIM     4096
#define BM      128
#define BN      128
#define BK      64                     // halves per chunk = 128 bytes per row
#define STAGES  3
#define NT      256
#define NC      (DIM / BK)             // 64 k-chunks
#define AB_TILE (BM * BK * 2)          // 16384 bytes per matrix per stage
#define STAGE_BYTES (2 * AB_TILE)      // 32768
#define SMEM_TOTAL  (STAGES * STAGE_BYTES)  // 98304

// ------------------------------------------------------------------ scratch
__device__ __half g_Xh[(size_t)DIM * DIM];
__device__ __half g_Wh[(size_t)DIM * DIM];

// ------------------------------------------------------------------ helpers
__device__ __forceinline__ uint32_t smem_u32(const void* p) {
    uint32_t a;
    asm("{ .reg .u64 t; cvta.to.shared.u64 t, %1; cvt.u32.u64 %0, t; }" : "=r"(a) : "l"(p));
    return a;
}
__device__ __forceinline__ void cp16(uint32_t saddr, const void* gaddr) {
    asm volatile("cp.async.cg.shared.global [%0], [%1], 16;"
                 :: "r"(saddr), "l"(gaddr) : "memory");
}
__device__ __forceinline__ void cp_commit() {
    asm volatile("cp.async.commit_group;" ::: "memory");
}
template <int N>
__device__ __forceinline__ void cp_wait() {
    asm volatile("cp.async.wait_group %0;" :: "n"(N) : "memory");
}
__device__ __forceinline__ void ldsm4(uint32_t* r, uint32_t addr) {
    asm volatile("ldmatrix.sync.aligned.m8n8.x4.shared.b16 {%0,%1,%2,%3}, [%4];"
                 : "=r"(r[0]), "=r"(r[1]), "=r"(r[2]), "=r"(r[3]) : "r"(addr));
}
__device__ __forceinline__ void mma_f16(float* d, const uint32_t* a, const uint32_t* b) {
    asm volatile(
        "mma.sync.aligned.m16n8k16.row.col.f32.f16.f16.f32 "
        "{%0,%1,%2,%3}, {%4,%5,%6,%7}, {%8,%9}, {%0,%1,%2,%3};"
        : "+f"(d[0]), "+f"(d[1]), "+f"(d[2]), "+f"(d[3])
        : "r"(a[0]), "r"(a[1]), "r"(a[2]), "r"(a[3]), "r"(b[0]), "r"(b[1]));
}

// ------------------------------------------------------------------ prep kernel
// 8 floats -> 8 halves per thread (read 2x float4, write one 16B uint4)
__global__ void __launch_bounds__(256) to_half_kernel(const float* __restrict__ in,
                                                      __half* __restrict__ outp) {
    size_t i = ((size_t)blockIdx.x * blockDim.x + threadIdx.x) * 8;
    float4 v0 = *reinterpret_cast<const float4*>(in + i);
    float4 v1 = *reinterpret_cast<const float4*>(in + i + 4);
    __half2 h0 = __floats2half2_rn(v0.x, v0.y);
    __half2 h1 = __floats2half2_rn(v0.z, v0.w);
    __half2 h2 = __floats2half2_rn(v1.x, v1.y);
    __half2 h3 = __floats2half2_rn(v1.z, v1.w);
    uint4 o;
    o.x = *reinterpret_cast<uint32_t*>(&h0);
    o.y = *reinterpret_cast<uint32_t*>(&h1);
    o.z = *reinterpret_cast<uint32_t*>(&h2);
    o.w = *reinterpret_cast<uint32_t*>(&h3);
    *reinterpret_cast<uint4*>(outp + i) = o;
}

// ------------------------------------------------------------------ main kernel
__global__ void __launch_bounds__(NT, 2)
resfc_mma_f16_gemm(const __half* __restrict__ Ah,   // fp16 X
                   const __half* __restrict__ Bh,   // fp16 W
                   const float* __restrict__ X,     // original X (residual)
                   const float* __restrict__ beta,
                   const float* __restrict__ beta_res,
                   float* __restrict__ out)
{
    extern __shared__ __align__(1024) char smem[];
    const uint32_t sbase = smem_u32(smem);
    const int tid = threadIdx.x;
    const int l   = tid & 31;
    const int wid = tid >> 5;
    const int warpM = (wid & 1) * 64;     // 2 warps in M
    const int warpN = (wid >> 1) * 32;    // 4 warps in N
    const int bm = blockIdx.y * BM;
    const int bn = blockIdx.x * BN;

    // ---- cp.async mapping: 256 threads x 4 passes x (A16B + B16B) per stage
    const int grow = tid >> 3;            // row 0..31 (+32 per pass)
    const int gcol = tid & 7;             // 16B granule within 128B row
    const __half* gA = Ah + (size_t)(bm + grow) * DIM + gcol * 8;
    const __half* gB = Bh + (size_t)(bn + grow) * DIM + gcol * 8;
    const uint32_t scol = (uint32_t)(gcol * 16);

    // ---- ldmatrix per-thread terms (SW128 swizzle within tile)
    const uint32_t xorv   = (uint32_t)(l & 7) << 4;
    const uint32_t aRow   = (uint32_t)(warpM + (l & 15));
    const uint32_t aByteH = (uint32_t)(l & 16);            // 0 or 16
    const uint32_t bRow   = (uint32_t)(warpN + (l & 7) + ((l >> 1) & 8));
    const uint32_t bByteH = (uint32_t)((l & 8) << 1);      // 0 or 16

    float acc[4][4][4];
    #pragma unroll
    for (int i = 0; i < 4; ++i)
        #pragma unroll
        for (int j = 0; j < 4; ++j)
            #pragma unroll
            for (int k = 0; k < 4; ++k)
                acc[i][j][k] = 0.0f;

    // -------- stage loader --------
    #define ISSUE(c, stage) do {                                              \
        const uint32_t sa_ = sbase + (uint32_t)(stage) * STAGE_BYTES;         \
        const __half* ga_ = gA + (size_t)(c) * BK;                            \
        const __half* gb_ = gB + (size_t)(c) * BK;                            \
        _Pragma("unroll")                                                     \
        for (int p_ = 0; p_ < 4; ++p_) {                                      \
            const uint32_t r_  = (uint32_t)(grow + p_ * 32);                  \
            const uint32_t so_ = r_ * 128 + (scol ^ ((r_ & 7) << 4));         \
            cp16(sa_ + so_,            ga_ + (size_t)p_ * 32 * DIM);          \
            cp16(sa_ + AB_TILE + so_,  gb_ + (size_t)p_ * 32 * DIM);          \
        }                                                                     \
    } while (0)

    // -------- prologue: fill STAGES-1 stages --------
    ISSUE(0, 0); cp_commit();
    ISSUE(1, 1); cp_commit();

    int stage = 0;
    for (int c = 0; c < NC; ++c) {
        cp_wait<STAGES - 2>();
        __syncthreads();

        const uint32_t aBase = sbase + (uint32_t)stage * STAGE_BYTES + aRow * 128;
        const uint32_t bBase = sbase + (uint32_t)stage * STAGE_BYTES + AB_TILE + bRow * 128;

        #pragma unroll
        for (int s = 0; s < 4; ++s) {       // 4 x k16 per 64-half chunk
            uint32_t aF[4][4];
            uint32_t bF[4][2];
            const uint32_t aoff = ((uint32_t)(s * 32) + aByteH) ^ xorv;
            const uint32_t boff = ((uint32_t)(s * 32) + bByteH) ^ xorv;
            #pragma unroll
            for (int t = 0; t < 4; ++t)
                ldsm4(aF[t], aBase + (uint32_t)t * 2048 + aoff);
            #pragma unroll
            for (int u = 0; u < 2; ++u) {
                uint32_t r[4];
                ldsm4(r, bBase + (uint32_t)u * 2048 + boff);
                bF[2 * u][0]     = r[0];  bF[2 * u][1]     = r[1];
                bF[2 * u + 1][0] = r[2];  bF[2 * u + 1][1] = r[3];
            }
            #pragma unroll
            for (int mt = 0; mt < 4; ++mt)
                #pragma unroll
                for (int nt = 0; nt < 4; ++nt)
                    mma_f16(acc[mt][nt], aF[mt], bF[nt]);
        }

        __syncthreads();
        const int cn = c + STAGES - 1;
        if (cn < NC) {
            const int sn = (stage + STAGES - 1) % STAGES;
            ISSUE(cn, sn);
        }
        cp_commit();
        if (++stage == STAGES) stage = 0;
    }
    #undef ISSUE

    // -------- fused epilogue --------
    const float one_mb = 1.0f - beta[0];
    const int colB = bn + warpN + 2 * (l & 3);

    float2 br2[4];
    #pragma unroll
    for (int nt = 0; nt < 4; ++nt)
        br2[nt] = *reinterpret_cast<const float2*>(beta_res + colB + nt * 8);

    #pragma unroll
    for (int mt = 0; mt < 4; ++mt) {
        #pragma unroll
        for (int h = 0; h < 2; ++h) {
            const int row = bm + warpM + mt * 16 + (l >> 2) + h * 8;
            const float* xr  = X   + (size_t)row * DIM + colB;
            float*       orw = out + (size_t)row * DIM + colB;
            #pragma unroll
            for (int nt = 0; nt < 4; ++nt) {
                float2 xv = *reinterpret_cast<const float2*>(xr + nt * 8);
                const float d0 = acc[mt][nt][h * 2 + 0];
                const float d1 = acc[mt][nt][h * 2 + 1];
                const float o0 = fmaxf(one_mb + d0, 0.0f);
                const float o1 = fmaxf(one_mb + d1, 0.0f);
                const float r0 = fmaxf(1.0f - (br2[nt].x - (xv.x + o0)), 0.0f);
                const float r1 = fmaxf(1.0f - (br2[nt].y - (xv.y + o1)), 0.0f);
                *reinterpret_cast<float2*>(orw + nt * 8) = make_float2(r0, r1);
            }
        }
    }
}

// ------------------------------------------------------------------ host side
extern "C" void kernel_launch(void* const* d_in, const int* in_sizes, int n_in,
                              void* d_out, int out_size)
{
    const float* X        = (const float*)d_in[0];
    const float* W        = (const float*)d_in[1];
    const float* beta     = (const float*)d_in[2];
    const float* beta_res = (const float*)d_in[3];
    float* out            = (float*)d_out;

    void *pXh = nullptr, *pWh = nullptr;
    cudaGetSymbolAddress(&pXh, g_Xh);
    cudaGetSymbolAddress(&pWh, g_Wh);

    to_half_kernel<<<DIM * DIM / (256 * 8), 256>>>(X, (__half*)pXh);
    to_half_kernel<<<DIM * DIM / (256 * 8), 256>>>(W, (__half*)pWh);

    cudaFuncSetAttribute(resfc_mma_f16_gemm,
                         cudaFuncAttributeMaxDynamicSharedMemorySize, SMEM_TOTAL);
    dim3 grid(DIM / BN, DIM / BM);   // 32 x 32
    resfc_mma_f16_gemm<<<grid, NT, SMEM_TOTAL>>>((const __half*)pXh, (const __half*)pWh,
                                                 X, beta, beta_res, out);
}